// round 14
// baseline (speedup 1.0000x reference)
#include <cuda_runtime.h>
#include <cuda_fp16.h>
#include <cstdint>
#include <cstddef>

#define NROWS 8192
#define HDIM  1024
#define KDIM  4096
#define NBITS 14
#define NLOG  28
#define BM 128
#define BN 128
#define BK 64                          // halves per k-tile (128 B rows, SW128)
#define NTSEG 16                       // k-tiles per segment = 1024/64
#define NSTAGE 3
#define STAGEB 32768                   // A 16KB + B 16KB
#define GEMM_DYN (NSTAGE * STAGEB)
#define IDX_DYN  (NLOG * HDIM * 4)
#define PSZ ((size_t)NROWS * HDIM)

__device__ int    g_idx1[NROWS];
__device__ int    g_idx2[NROWS];
__device__ float  g_bias[HDIM];
__device__ __align__(256) __half g_part[4 * PSZ];              // split-K partials, fp16
__device__ __align__(256) __half g_ah[(size_t)NROWS * KDIM];   // gathered A, fp16
__device__ __align__(256) __half g_wh[(size_t)HDIM * KDIM];    // weights [n][4*1024], fp16

// ---------------- helpers ----------------
__device__ __forceinline__ uint32_t smem_u32(const void* p) {
    return (uint32_t)__cvta_generic_to_shared(p);
}
__device__ __forceinline__ void cpa16(uint32_t dst, const void* src) {
    asm volatile("cp.async.ca.shared.global [%0], [%1], 16;" :: "r"(dst), "l"(src));
}
__device__ __forceinline__ void cpa_commit() {
    asm volatile("cp.async.commit_group;" ::: "memory");
}
__device__ __forceinline__ void mma_f16(float* d, const uint32_t* a, uint32_t b0, uint32_t b1) {
    asm volatile(
        "mma.sync.aligned.m16n8k16.row.col.f32.f16.f16.f32 "
        "{%0,%1,%2,%3}, {%4,%5,%6,%7}, {%8,%9}, {%0,%1,%2,%3};"
        : "+f"(d[0]), "+f"(d[1]), "+f"(d[2]), "+f"(d[3])
        : "r"(a[0]), "r"(a[1]), "r"(a[2]), "r"(a[3]), "r"(b0), "r"(b1));
}
__device__ __forceinline__ void ldsm4(uint32_t* r, uint32_t addr) {
    asm volatile("ldmatrix.sync.aligned.m8n8.x4.shared.b16 {%0,%1,%2,%3}, [%4];"
                 : "=r"(r[0]), "=r"(r[1]), "=r"(r[2]), "=r"(r[3]) : "r"(addr));
}

// =============== Kernel 1: logits -> indices ===============
__global__ void __launch_bounds__(256) idx_kernel(const float* __restrict__ h_prev,
                                                  const float* __restrict__ Mw,
                                                  const float* __restrict__ Mb) {
    extern __shared__ float sMw[];
    int tid = threadIdx.x;
    {
        const float4* s = (const float4*)Mw;
        float4* d = (float4*)sMw;
        for (int i = tid; i < NLOG * HDIM / 4; i += 256) d[i] = s[i];
    }
    __syncthreads();
    int lane = tid & 31, w = tid >> 5;
    for (int rr = 0; rr < 4; ++rr) {
        int row = blockIdx.x * 32 + w * 4 + rr;
        const float* h = h_prev + (size_t)row * HDIM;
        float hreg[32];
#pragma unroll
        for (int j = 0; j < 32; ++j) hreg[j] = h[lane + 32 * j];
        int v1 = 0, v2 = 0;
        for (int l = 0; l < NLOG; ++l) {
            const float* m = sMw + l * HDIM;
            float acc = 0.f;
#pragma unroll
            for (int j = 0; j < 32; ++j) acc += hreg[j] * m[lane + 32 * j];
#pragma unroll
            for (int o = 16; o; o >>= 1) acc += __shfl_xor_sync(0xffffffffu, acc, o);
            if (lane == 0 && acc + Mb[l] > 0.f) {
                if (l < NBITS) v1 |= 1 << (NBITS - 1 - l);
                else           v2 |= 1 << (2 * NBITS - 1 - l);
            }
        }
        if (lane == 0) {
            g_idx1[row] = v1 < 8191 ? v1 : 8191;
            g_idx2[row] = v2 > 8192 ? v2 : 8192;
        }
    }
}

// =============== Kernel 2: combined bias ===============
__global__ void bias_kernel(const float* __restrict__ Wb, const float* __restrict__ Ub,
                            const float* __restrict__ Qrb, const float* __restrict__ Qlb) {
    int i = blockIdx.x * 256 + threadIdx.x;
    g_bias[i] = Wb[i] + Ub[i] + Qrb[i] + Qlb[i];
}

// =============== Kernel 3: weights -> fp16, layout [n][4*1024] ===============
__global__ void __launch_bounds__(256) convert_w(const float* __restrict__ Ww,
                                                 const float* __restrict__ Uw,
                                                 const float* __restrict__ Qrw,
                                                 const float* __restrict__ Qlw) {
    int i = blockIdx.x * 256 + threadIdx.x;      // float4 index, 1M total
    int n  = i >> 10;
    int k4 = i & 1023;
    int kg = k4 * 4;
    int seg = kg >> 10;
    int k   = kg & 1023;
    const float* w = (seg == 0) ? Ww : (seg == 1) ? Uw : (seg == 2) ? Qrw : Qlw;
    float4 v = *(const float4*)(w + (size_t)n * HDIM + k);
    __half2 h0 = __floats2half2_rn(v.x, v.y);
    __half2 h1 = __floats2half2_rn(v.z, v.w);
    uint2 o = make_uint2(*(uint32_t*)&h0, *(uint32_t*)&h1);
    *(uint2*)(g_wh + (size_t)n * KDIM + kg) = o;
}

// =============== Kernel 4: gather + fp16 A matrix ===============
__global__ void __launch_bounds__(256) convert_a(const float* __restrict__ x,
                                                 const float* __restrict__ h_prev,
                                                 const float* __restrict__ memory) {
    const int b = blockIdx.x, tid = threadIdx.x;
    const float* srcs[4];
    srcs[0] = x      + (size_t)b * HDIM;
    srcs[1] = h_prev + (size_t)b * HDIM;
    srcs[2] = memory + (size_t)g_idx1[b] * HDIM;
    srcs[3] = memory + (size_t)g_idx2[b] * HDIM;
    __half* dst = g_ah + (size_t)b * KDIM;
#pragma unroll
    for (int s = 0; s < 4; ++s) {
        float4 v = ((const float4*)srcs[s])[tid];
        __half2 h0 = __floats2half2_rn(v.x, v.y);
        __half2 h1 = __floats2half2_rn(v.z, v.w);
        uint2 o = make_uint2(*(uint32_t*)&h0, *(uint32_t*)&h1);
        ((uint2*)(dst + s * HDIM))[tid] = o;
    }
}

// =============== Kernel 5: fp16 mma.sync GEMM, split-K=4, 64x64 warp tiles ===============
__global__ void __launch_bounds__(128, 2) gemm_kernel() {
    extern __shared__ __half smh[];          // [3][A 128x64h SW128 | B 128x64h SW128]

    const int tid = threadIdx.x;
    const int bn0 = blockIdx.x * BN, bm0 = blockIdx.y * BM;
    const int seg = blockIdx.z;              // K segment: 0..3
    const uint32_t smb = smem_u32(smh);

    // ---- loader mapping: 1 thread/row, 8x16B chunks each for A and B ----
    const int lrow = tid;                    // 0..127
    const __half* aSrc = g_ah + (size_t)(bm0 + lrow) * KDIM + seg * 1024;
    const __half* bSrc = g_wh + (size_t)(bn0 + lrow) * KDIM + seg * 1024;
    const uint32_t lmask  = (uint32_t)((lrow & 7) << 4);
    const uint32_t rowOff = (uint32_t)lrow * 128;

    auto issue = [&](int kt, int s) {
        const uint32_t base = smb + (uint32_t)s * STAGEB;
        const __half* as = aSrc + kt * BK;
        const __half* bs = bSrc + kt * BK;
#pragma unroll
        for (int j = 0; j < 8; ++j) {
            const uint32_t sw = rowOff + (((uint32_t)(j * 16)) ^ lmask);
            cpa16(base + sw,         as + j * 8);
            cpa16(base + 16384 + sw, bs + j * 8);
        }
        cpa_commit();
    };

    issue(0, 0); issue(1, 1);

    // ---- fragment addressing: 2x2 warps, each 64x64 ----
    const int lane = tid & 31, warp = tid >> 5;
    const int wm = warp & 1;                 // m0 = wm*64
    const int wn = warp >> 1;                // n0 = wn*64
    const int l7 = lane & 7;
    const uint32_t xm = (uint32_t)(l7 << 4);
    const int rAb = wm * 64 + (((lane & 15) >> 3) << 3) + l7;      // + mt*16
    const uint32_t hiA = (lane >= 16) ? 16u : 0u;
    const int rBb = wn * 64 + ((lane >= 16) ? 8 : 0) + l7;         // + p*16
    const uint32_t hiB = ((lane & 15) >= 8) ? 16u : 0u;

    float acc[4][8][4];
#pragma unroll
    for (int mt = 0; mt < 4; ++mt)
#pragma unroll
        for (int nt = 0; nt < 8; ++nt)
#pragma unroll
            for (int i = 0; i < 4; ++i) acc[mt][nt][i] = 0.f;

    for (int kt = 0; kt < NTSEG; ++kt) {
        if (kt >= NTSEG - 2) asm volatile("cp.async.wait_group 0;" ::: "memory");
        else                 asm volatile("cp.async.wait_group 1;" ::: "memory");
        __syncthreads();
        if (kt + 2 < NTSEG) issue(kt + 2, (kt + 2) % NSTAGE);  // stage freed at iter kt-1

        const uint32_t sA = smb + (uint32_t)(kt % NSTAGE) * STAGEB;
        const uint32_t sB = sA + 16384;

#pragma unroll
        for (int q = 0; q < 4; ++q) {                        // 4 x k16 per tile
            uint32_t a[4][4];
#pragma unroll
            for (int mt = 0; mt < 4; ++mt)
                ldsm4(a[mt], sA + (uint32_t)(rAb + mt * 16) * 128
                             + (((uint32_t)(q * 32) + hiA) ^ xm));
#pragma unroll
            for (int p = 0; p < 4; ++p) {
                uint32_t b[4];                               // b0/b1 of nt=2p, 2p+1
                ldsm4(b, sB + (uint32_t)(rBb + p * 16) * 128
                          + (((uint32_t)(q * 32) + hiB) ^ xm));
#pragma unroll
                for (int mt = 0; mt < 4; ++mt) {
                    mma_f16(acc[mt][2 * p],     a[mt], b[0], b[1]);
                    mma_f16(acc[mt][2 * p + 1], a[mt], b[2], b[3]);
                }
            }
        }
    }

    // ---- epilogue: fp16 partials ----
    const int g = lane >> 2, c = lane & 3;
    __half* pbase = g_part + (size_t)seg * PSZ;
#pragma unroll
    for (int mt = 0; mt < 4; ++mt) {
        const int row0 = bm0 + wm * 64 + mt * 16 + g;
#pragma unroll
        for (int nt = 0; nt < 8; ++nt) {
            const int col = bn0 + wn * 64 + nt * 8 + c * 2;
            __half2 h0 = __floats2half2_rn(acc[mt][nt][0], acc[mt][nt][1]);
            __half2 h1 = __floats2half2_rn(acc[mt][nt][2], acc[mt][nt][3]);
            *(uint32_t*)(pbase + (size_t)row0 * HDIM + col)       = *(uint32_t*)&h0;
            *(uint32_t*)(pbase + (size_t)(row0 + 8) * HDIM + col) = *(uint32_t*)&h1;
        }
    }
}

// =============== Kernel 6: partial-sum + bias + layernorm + sigmoid ===============
__global__ void __launch_bounds__(256) ln_kernel(const float* __restrict__ gamma,
                                                 const float* __restrict__ beta,
                                                 float* __restrict__ out) {
    __shared__ float red[16];
    const int row = blockIdx.x, tid = threadIdx.x;
    float4 v = ((const float4*)g_bias)[tid];
#pragma unroll
    for (int s = 0; s < 4; ++s) {
        uint2 u = ((const uint2*)(g_part + (size_t)s * PSZ + (size_t)row * HDIM))[tid];
        float2 fa = __half22float2(*(__half2*)&u.x);
        float2 fb = __half22float2(*(__half2*)&u.y);
        v.x += fa.x; v.y += fa.y; v.z += fb.x; v.w += fb.y;
    }
    float s = v.x + v.y + v.z + v.w;
    float q = v.x * v.x + v.y * v.y + v.z * v.z + v.w * v.w;
#pragma unroll
    for (int o = 16; o; o >>= 1) {
        s += __shfl_xor_sync(0xffffffffu, s, o);
        q += __shfl_xor_sync(0xffffffffu, q, o);
    }
    const int lane = tid & 31, w = tid >> 5;
    if (lane == 0) { red[w] = s; red[8 + w] = q; }
    __syncthreads();
    if (tid < 8) {
        s = red[tid]; q = red[8 + tid];
#pragma unroll
        for (int o = 4; o; o >>= 1) {
            s += __shfl_xor_sync(0xffu, s, o);
            q += __shfl_xor_sync(0xffu, q, o);
        }
        if (tid == 0) { red[0] = s; red[8] = q; }
    }
    __syncthreads();
    const float mu  = red[0] * (1.f / HDIM);
    const float var = red[8] * (1.f / HDIM) - mu * mu;
    const float rs  = rsqrtf(var + 1e-5f);
    float4 gm = ((const float4*)gamma)[tid];
    float4 bt = ((const float4*)beta)[tid];
    float4 o4;
    o4.x = 1.f / (1.f + __expf(-((v.x - mu) * rs * gm.x + bt.x)));
    o4.y = 1.f / (1.f + __expf(-((v.y - mu) * rs * gm.y + bt.y)));
    o4.z = 1.f / (1.f + __expf(-((v.z - mu) * rs * gm.z + bt.z)));
    o4.w = 1.f / (1.f + __expf(-((v.w - mu) * rs * gm.w + bt.w)));
    ((float4*)(out + (size_t)row * HDIM))[tid] = o4;
}

// =============== host launch ===============
extern "C" void kernel_launch(void* const* d_in, const int* in_sizes, int n_in,
                              void* d_out, int out_size) {
    const float* x     = (const float*)d_in[0];
    const float* h     = (const float*)d_in[1];
    const float* mem   = (const float*)d_in[2];
    const float* Ww    = (const float*)d_in[3];
    const float* Wb    = (const float*)d_in[4];
    const float* Uw    = (const float*)d_in[5];
    const float* Ub    = (const float*)d_in[6];
    const float* Mw    = (const float*)d_in[7];
    const float* Mb    = (const float*)d_in[8];
    const float* Qrw   = (const float*)d_in[9];
    const float* Qrb   = (const float*)d_in[10];
    const float* Qlw   = (const float*)d_in[11];
    const float* Qlb   = (const float*)d_in[12];
    const float* gamma = (const float*)d_in[13];
    const float* beta  = (const float*)d_in[14];
    float* out = (float*)d_out;

    cudaFuncSetAttribute(idx_kernel,  cudaFuncAttributeMaxDynamicSharedMemorySize, IDX_DYN);
    cudaFuncSetAttribute(gemm_kernel, cudaFuncAttributeMaxDynamicSharedMemorySize, GEMM_DYN);

    bias_kernel<<<HDIM / 256, 256>>>(Wb, Ub, Qrb, Qlb);
    convert_w<<<HDIM * KDIM / 4 / 256, 256>>>(Ww, Uw, Qrw, Qlw);
    idx_kernel<<<NROWS / 32, 256, IDX_DYN>>>(h, Mw, Mb);
    convert_a<<<NROWS, 256>>>(x, h, mem);
    gemm_kernel<<<dim3(HDIM / BN, NROWS / BM, 4), 128, GEMM_DYN>>>();
    ln_kernel<<<NROWS, 256>>>(gamma, beta, out);
}

// round 15
// speedup vs baseline: 1.2391x; 1.2391x over previous
#include <cuda_runtime.h>
#include <cuda_fp16.h>
#include <cstdint>
#include <cstddef>

#define NROWS 8192
#define HDIM  1024
#define KDIM  4096
#define NBITS 14
#define NLOG  28
#define BM 128
#define BN 128
#define BK 64                          // halves per k-tile (128 B rows, SW128)
#define NTSEG 16                       // k-tiles per segment = 1024/64
#define NSTAGE 3
#define STAGEB 32768                   // A 16KB + B 16KB
#define GEMM_DYN (NSTAGE * STAGEB)
#define IDX_DYN  (NLOG * HDIM * 4)
#define PSZ ((size_t)NROWS * HDIM)

__device__ int    g_idx1[NROWS];
__device__ int    g_idx2[NROWS];
__device__ __align__(256) __half g_part[4 * PSZ];              // split-K partials, fp16
__device__ __align__(256) __half g_ah[(size_t)NROWS * KDIM];   // gathered A, fp16
__device__ __align__(256) __half g_wh[(size_t)HDIM * KDIM];    // weights [n][4*1024], fp16

// ---------------- helpers ----------------
__device__ __forceinline__ uint32_t smem_u32(const void* p) {
    return (uint32_t)__cvta_generic_to_shared(p);
}
__device__ __forceinline__ void cpa16(uint32_t dst, const void* src) {
    asm volatile("cp.async.ca.shared.global [%0], [%1], 16;" :: "r"(dst), "l"(src));
}
__device__ __forceinline__ void cpa_commit() {
    asm volatile("cp.async.commit_group;" ::: "memory");
}
__device__ __forceinline__ void mma_f16(float* d, const uint32_t* a, uint32_t b0, uint32_t b1) {
    asm volatile(
        "mma.sync.aligned.m16n8k16.row.col.f32.f16.f16.f32 "
        "{%0,%1,%2,%3}, {%4,%5,%6,%7}, {%8,%9}, {%0,%1,%2,%3};"
        : "+f"(d[0]), "+f"(d[1]), "+f"(d[2]), "+f"(d[3])
        : "r"(a[0]), "r"(a[1]), "r"(a[2]), "r"(a[3]), "r"(b0), "r"(b1));
}
__device__ __forceinline__ void ldsm4(uint32_t* r, uint32_t addr) {
    asm volatile("ldmatrix.sync.aligned.m8n8.x4.shared.b16 {%0,%1,%2,%3}, [%4];"
                 : "=r"(r[0]), "=r"(r[1]), "=r"(r[2]), "=r"(r[3]) : "r"(addr));
}

// =============== Kernel 1: logits -> indices (float4 LDS) ===============
__global__ void __launch_bounds__(256) idx_kernel(const float* __restrict__ h_prev,
                                                  const float* __restrict__ Mw,
                                                  const float* __restrict__ Mb) {
    extern __shared__ float sMw[];
    int tid = threadIdx.x;
    {
        const float4* s = (const float4*)Mw;
        float4* d = (float4*)sMw;
        for (int i = tid; i < NLOG * HDIM / 4; i += 256) d[i] = s[i];
    }
    __syncthreads();
    int lane = tid & 31, w = tid >> 5;
    for (int rr = 0; rr < 4; ++rr) {
        int row = blockIdx.x * 32 + w * 4 + rr;
        const float4* h4 = (const float4*)(h_prev + (size_t)row * HDIM);
        float4 hreg[8];
#pragma unroll
        for (int j = 0; j < 8; ++j) hreg[j] = h4[lane + 32 * j];
        int v1 = 0, v2 = 0;
        for (int l = 0; l < NLOG; ++l) {
            const float4* m4 = (const float4*)(sMw + l * HDIM);
            float acc = 0.f;
#pragma unroll
            for (int j = 0; j < 8; ++j) {
                float4 m = m4[lane + 32 * j];
                acc += hreg[j].x * m.x + hreg[j].y * m.y
                     + hreg[j].z * m.z + hreg[j].w * m.w;
            }
#pragma unroll
            for (int o = 16; o; o >>= 1) acc += __shfl_xor_sync(0xffffffffu, acc, o);
            if (lane == 0 && acc + Mb[l] > 0.f) {
                if (l < NBITS) v1 |= 1 << (NBITS - 1 - l);
                else           v2 |= 1 << (2 * NBITS - 1 - l);
            }
        }
        if (lane == 0) {
            g_idx1[row] = v1 < 8191 ? v1 : 8191;
            g_idx2[row] = v2 > 8192 ? v2 : 8192;
        }
    }
}

// =============== Kernel 2: weights -> fp16, layout [n][4*1024] ===============
__global__ void __launch_bounds__(256) convert_w(const float* __restrict__ Ww,
                                                 const float* __restrict__ Uw,
                                                 const float* __restrict__ Qrw,
                                                 const float* __restrict__ Qlw) {
    int i = blockIdx.x * 256 + threadIdx.x;      // float4 index, 1M total
    int n  = i >> 10;
    int k4 = i & 1023;
    int kg = k4 * 4;
    int seg = kg >> 10;
    int k   = kg & 1023;
    const float* w = (seg == 0) ? Ww : (seg == 1) ? Uw : (seg == 2) ? Qrw : Qlw;
    float4 v = *(const float4*)(w + (size_t)n * HDIM + k);
    __half2 h0 = __floats2half2_rn(v.x, v.y);
    __half2 h1 = __floats2half2_rn(v.z, v.w);
    uint2 o = make_uint2(*(uint32_t*)&h0, *(uint32_t*)&h1);
    *(uint2*)(g_wh + (size_t)n * KDIM + kg) = o;
}

// =============== Kernel 3: gather + fp16 A matrix ===============
__global__ void __launch_bounds__(256) convert_a(const float* __restrict__ x,
                                                 const float* __restrict__ h_prev,
                                                 const float* __restrict__ memory) {
    const int b = blockIdx.x, tid = threadIdx.x;
    const float* srcs[4];
    srcs[0] = x      + (size_t)b * HDIM;
    srcs[1] = h_prev + (size_t)b * HDIM;
    srcs[2] = memory + (size_t)g_idx1[b] * HDIM;
    srcs[3] = memory + (size_t)g_idx2[b] * HDIM;
    __half* dst = g_ah + (size_t)b * KDIM;
#pragma unroll
    for (int s = 0; s < 4; ++s) {
        float4 v = ((const float4*)srcs[s])[tid];
        __half2 h0 = __floats2half2_rn(v.x, v.y);
        __half2 h1 = __floats2half2_rn(v.z, v.w);
        uint2 o = make_uint2(*(uint32_t*)&h0, *(uint32_t*)&h1);
        ((uint2*)(dst + s * HDIM))[tid] = o;
    }
}

// =============== Kernel 4: fp16 mma.sync GEMM, split-K=4 by segment ===============
__global__ void __launch_bounds__(256, 2) gemm_kernel() {
    extern __shared__ __half smh[];          // [3][A 128x64h SW128 | B 128x64h SW128]

    const int tid = threadIdx.x;
    const int bn0 = blockIdx.x * BN, bm0 = blockIdx.y * BM;
    const int seg = blockIdx.z;              // K segment: 0..3
    const uint32_t smb = smem_u32(smh);

    // ---- loader mapping: 2 threads/row, 4x16B chunks each ----
    const int lrow = tid >> 1;               // 0..127
    const int lh   = tid & 1;
    const __half* aSrc = g_ah + (size_t)(bm0 + lrow) * KDIM + seg * 1024 + lh * 32;
    const __half* bSrc = g_wh + (size_t)(bn0 + lrow) * KDIM + seg * 1024 + lh * 32;
    const uint32_t lmask  = (uint32_t)((lrow & 7) << 4);
    const uint32_t rowOff = (uint32_t)lrow * 128;

    auto issue = [&](int kt, int s) {
        const uint32_t base = smb + (uint32_t)s * STAGEB;
        const __half* as = aSrc + kt * BK;
        const __half* bs = bSrc + kt * BK;
#pragma unroll
        for (int j = 0; j < 4; ++j) {
            const uint32_t cb = (uint32_t)(lh * 64 + j * 16);
            const uint32_t sw = rowOff + (cb ^ lmask);
            cpa16(base + sw,         as + j * 8);
            cpa16(base + 16384 + sw, bs + j * 8);
        }
        cpa_commit();
    };

    issue(0, 0); issue(1, 1);

    // ---- fragment addressing (lane constants) ----
    const int lane = tid & 31, warp = tid >> 5;
    const int wm = warp & 3;                 // m0 = wm*32
    const int wn = warp >> 2;                // n0 = wn*64
    const int l7 = lane & 7;
    const uint32_t xm = (uint32_t)(l7 << 4);
    const int rAb = wm * 32 + (((lane & 15) >> 3) << 3) + l7;      // + mt*16
    const uint32_t hiA = (lane >= 16) ? 16u : 0u;
    const int rBb = wn * 64 + ((lane >= 16) ? 8 : 0) + l7;         // + p*16
    const uint32_t hiB = ((lane & 15) >= 8) ? 16u : 0u;

    float acc[2][8][4];
#pragma unroll
    for (int mt = 0; mt < 2; ++mt)
#pragma unroll
        for (int nt = 0; nt < 8; ++nt)
#pragma unroll
            for (int i = 0; i < 4; ++i) acc[mt][nt][i] = 0.f;

    for (int kt = 0; kt < NTSEG; ++kt) {
        if (kt >= NTSEG - 2) asm volatile("cp.async.wait_group 0;" ::: "memory");
        else                 asm volatile("cp.async.wait_group 1;" ::: "memory");
        __syncthreads();
        if (kt + 2 < NTSEG) issue(kt + 2, (kt + 2) % NSTAGE);  // stage freed at iter kt-1

        const uint32_t sA = smb + (uint32_t)(kt % NSTAGE) * STAGEB;
        const uint32_t sB = sA + 16384;

#pragma unroll
        for (int q = 0; q < 4; ++q) {                        // 4 x k16 per tile
            uint32_t a[2][4];
#pragma unroll
            for (int mt = 0; mt < 2; ++mt)
                ldsm4(a[mt], sA + (uint32_t)(rAb + mt * 16) * 128
                             + (((uint32_t)(q * 32) + hiA) ^ xm));
#pragma unroll
            for (int p = 0; p < 4; ++p) {
                uint32_t b[4];                               // b0/b1 of nt=2p, 2p+1
                ldsm4(b, sB + (uint32_t)(rBb + p * 16) * 128
                          + (((uint32_t)(q * 32) + hiB) ^ xm));
                mma_f16(acc[0][2 * p],     a[0], b[0], b[1]);
                mma_f16(acc[1][2 * p],     a[1], b[0], b[1]);
                mma_f16(acc[0][2 * p + 1], a[0], b[2], b[3]);
                mma_f16(acc[1][2 * p + 1], a[1], b[2], b[3]);
            }
        }
    }

    // ---- epilogue: fp16 partials ----
    const int g = lane >> 2, c = lane & 3;
    __half* pbase = g_part + (size_t)seg * PSZ;
#pragma unroll
    for (int mt = 0; mt < 2; ++mt) {
        const int row0 = bm0 + wm * 32 + mt * 16 + g;
#pragma unroll
        for (int nt = 0; nt < 8; ++nt) {
            const int col = bn0 + wn * 64 + nt * 8 + c * 2;
            __half2 h0 = __floats2half2_rn(acc[mt][nt][0], acc[mt][nt][1]);
            __half2 h1 = __floats2half2_rn(acc[mt][nt][2], acc[mt][nt][3]);
            *(uint32_t*)(pbase + (size_t)row0 * HDIM + col)       = *(uint32_t*)&h0;
            *(uint32_t*)(pbase + (size_t)(row0 + 8) * HDIM + col) = *(uint32_t*)&h1;
        }
    }
}

// =============== Kernel 5: partial-sum + bias + layernorm + sigmoid ===============
__global__ void __launch_bounds__(256) ln_kernel(const float* __restrict__ gamma,
                                                 const float* __restrict__ beta,
                                                 const float* __restrict__ Wb,
                                                 const float* __restrict__ Ub,
                                                 const float* __restrict__ Qrb,
                                                 const float* __restrict__ Qlb,
                                                 float* __restrict__ out) {
    __shared__ float red[16];
    const int row = blockIdx.x, tid = threadIdx.x;
    float4 b0 = ((const float4*)Wb)[tid];
    float4 b1 = ((const float4*)Ub)[tid];
    float4 b2 = ((const float4*)Qrb)[tid];
    float4 b3 = ((const float4*)Qlb)[tid];
    float4 v = make_float4(b0.x + b1.x + b2.x + b3.x,
                           b0.y + b1.y + b2.y + b3.y,
                           b0.z + b1.z + b2.z + b3.z,
                           b0.w + b1.w + b2.w + b3.w);
#pragma unroll
    for (int s = 0; s < 4; ++s) {
        uint2 u = ((const uint2*)(g_part + (size_t)s * PSZ + (size_t)row * HDIM))[tid];
        float2 fa = __half22float2(*(__half2*)&u.x);
        float2 fb = __half22float2(*(__half2*)&u.y);
        v.x += fa.x; v.y += fa.y; v.z += fb.x; v.w += fb.y;
    }
    float s = v.x + v.y + v.z + v.w;
    float q = v.x * v.x + v.y * v.y + v.z * v.z + v.w * v.w;
#pragma unroll
    for (int o = 16; o; o >>= 1) {
        s += __shfl_xor_sync(0xffffffffu, s, o);
        q += __shfl_xor_sync(0xffffffffu, q, o);
    }
    const int lane = tid & 31, w = tid >> 5;
    if (lane == 0) { red[w] = s; red[8 + w] = q; }
    __syncthreads();
    if (tid < 8) {
        s = red[tid]; q = red[8 + tid];
#pragma unroll
        for (int o = 4; o; o >>= 1) {
            s += __shfl_xor_sync(0xffu, s, o);
            q += __shfl_xor_sync(0xffu, q, o);
        }
        if (tid == 0) { red[0] = s; red[8] = q; }
    }
    __syncthreads();
    const float mu  = red[0] * (1.f / HDIM);
    const float var = red[8] * (1.f / HDIM) - mu * mu;
    const float rs  = rsqrtf(var + 1e-5f);
    float4 gm = ((const float4*)gamma)[tid];
    float4 bt = ((const float4*)beta)[tid];
    float4 o4;
    o4.x = 1.f / (1.f + __expf(-((v.x - mu) * rs * gm.x + bt.x)));
    o4.y = 1.f / (1.f + __expf(-((v.y - mu) * rs * gm.y + bt.y)));
    o4.z = 1.f / (1.f + __expf(-((v.z - mu) * rs * gm.z + bt.z)));
    o4.w = 1.f / (1.f + __expf(-((v.w - mu) * rs * gm.w + bt.w)));
    ((float4*)(out + (size_t)row * HDIM))[tid] = o4;
}

// =============== host launch ===============
extern "C" void kernel_launch(void* const* d_in, const int* in_sizes, int n_in,
                              void* d_out, int out_size) {
    const float* x     = (const float*)d_in[0];
    const float* h     = (const float*)d_in[1];
    const float* mem   = (const float*)d_in[2];
    const float* Ww    = (const float*)d_in[3];
    const float* Wb    = (const float*)d_in[4];
    const float* Uw    = (const float*)d_in[5];
    const float* Ub    = (const float*)d_in[6];
    const float* Mw    = (const float*)d_in[7];
    const float* Mb    = (const float*)d_in[8];
    const float* Qrw   = (const float*)d_in[9];
    const float* Qrb   = (const float*)d_in[10];
    const float* Qlw   = (const float*)d_in[11];
    const float* Qlb   = (const float*)d_in[12];
    const float* gamma = (const float*)d_in[13];
    const float* beta  = (const float*)d_in[14];
    float* out = (float*)d_out;

    cudaFuncSetAttribute(idx_kernel,  cudaFuncAttributeMaxDynamicSharedMemorySize, IDX_DYN);
    cudaFuncSetAttribute(gemm_kernel, cudaFuncAttributeMaxDynamicSharedMemorySize, GEMM_DYN);

    idx_kernel<<<NROWS / 32, 256, IDX_DYN>>>(h, Mw, Mb);
    convert_w<<<HDIM * KDIM / 4 / 256, 256>>>(Ww, Uw, Qrw, Qlw);
    convert_a<<<NROWS, 256>>>(x, h, mem);
    gemm_kernel<<<dim3(HDIM / BN, NROWS / BM, 4), 256, GEMM_DYN>>>();
    ln_kernel<<<NROWS, 256>>>(gamma, beta, Wb, Ub, Qrb, Qlb, out);
}

// round 17
// speedup vs baseline: 1.4915x; 1.2037x over previous
#include <cuda_runtime.h>
#include <cuda_fp16.h>
#include <cstdint>
#include <cstddef>

#define NROWS 8192
#define HDIM  1024
#define KDIM  4096
#define NBITS 14
#define NLOG  28
#define BM 128
#define BN 128
#define BK 64                          // halves per k-tile (128 B rows, SW128)
#define NTSEG 16                       // k-tiles per segment = 1024/64
#define NSTAGE 3
#define STAGEB 32768                   // A 16KB + B 16KB
#define GEMM_DYN (NSTAGE * STAGEB)
#define IDX_DYN  (NLOG * HDIM * 4)
#define PSZ ((size_t)NROWS * HDIM)

__device__ int    g_idx1[NROWS];
__device__ int    g_idx2[NROWS];
__device__ __align__(256) __half g_part[4 * PSZ];              // split-K partials, fp16
__device__ __align__(256) __half g_ah[(size_t)NROWS * KDIM];   // gathered A, fp16
__device__ __align__(256) __half g_wh[(size_t)HDIM * KDIM];    // weights [n][4*1024], fp16

// ---------------- helpers ----------------
__device__ __forceinline__ uint32_t smem_u32(const void* p) {
    return (uint32_t)__cvta_generic_to_shared(p);
}
__device__ __forceinline__ void cpa16(uint32_t dst, const void* src) {
    // .cg: bypass L1 (no L1 reuse exists for these tiles); global->L2->smem
    asm volatile("cp.async.cg.shared.global [%0], [%1], 16;" :: "r"(dst), "l"(src));
}
__device__ __forceinline__ void cpa_commit() {
    asm volatile("cp.async.commit_group;" ::: "memory");
}
__device__ __forceinline__ void mma_f16(float* d, const uint32_t* a, uint32_t b0, uint32_t b1) {
    asm volatile(
        "mma.sync.aligned.m16n8k16.row.col.f32.f16.f16.f32 "
        "{%0,%1,%2,%3}, {%4,%5,%6,%7}, {%8,%9}, {%0,%1,%2,%3};"
        : "+f"(d[0]), "+f"(d[1]), "+f"(d[2]), "+f"(d[3])
        : "r"(a[0]), "r"(a[1]), "r"(a[2]), "r"(a[3]), "r"(b0), "r"(b1));
}
__device__ __forceinline__ void ldsm4(uint32_t* r, uint32_t addr) {
    asm volatile("ldmatrix.sync.aligned.m8n8.x4.shared.b16 {%0,%1,%2,%3}, [%4];"
                 : "=r"(r[0]), "=r"(r[1]), "=r"(r[2]), "=r"(r[3]) : "r"(addr));
}

// =============== Kernel 1: logits -> indices (4 rows/warp register blocking) ===============
__global__ void __launch_bounds__(256) idx_kernel(const float* __restrict__ h_prev,
                                                  const float* __restrict__ Mw,
                                                  const float* __restrict__ Mb) {
    extern __shared__ float sMw[];
    int tid = threadIdx.x;
    {
        const float4* s = (const float4*)Mw;
        float4* d = (float4*)sMw;
        for (int i = tid; i < NLOG * HDIM / 4; i += 256) d[i] = s[i];
    }
    __syncthreads();
    const int lane = tid & 31, w = tid >> 5;
    const int row0 = blockIdx.x * 32 + w * 4;

    float4 hreg[4][8];
#pragma unroll
    for (int r = 0; r < 4; ++r) {
        const float4* h4 = (const float4*)(h_prev + (size_t)(row0 + r) * HDIM);
#pragma unroll
        for (int j = 0; j < 8; ++j) hreg[r][j] = h4[lane + 32 * j];
    }

    int v1[4] = {0, 0, 0, 0}, v2[4] = {0, 0, 0, 0};
    for (int l = 0; l < NLOG; ++l) {
        const float4* m4 = (const float4*)(sMw + l * HDIM);
        float acc[4] = {0.f, 0.f, 0.f, 0.f};
#pragma unroll
        for (int j = 0; j < 8; ++j) {
            float4 m = m4[lane + 32 * j];
#pragma unroll
            for (int r = 0; r < 4; ++r)
                acc[r] += hreg[r][j].x * m.x + hreg[r][j].y * m.y
                        + hreg[r][j].z * m.z + hreg[r][j].w * m.w;
        }
#pragma unroll
        for (int o = 16; o; o >>= 1)
#pragma unroll
            for (int r = 0; r < 4; ++r)
                acc[r] += __shfl_xor_sync(0xffffffffu, acc[r], o);
        if (lane == 0) {
            float mb = Mb[l];
#pragma unroll
            for (int r = 0; r < 4; ++r) {
                if (acc[r] + mb > 0.f) {
                    if (l < NBITS) v1[r] |= 1 << (NBITS - 1 - l);
                    else           v2[r] |= 1 << (2 * NBITS - 1 - l);
                }
            }
        }
    }
    if (lane == 0) {
#pragma unroll
        for (int r = 0; r < 4; ++r) {
            g_idx1[row0 + r] = v1[r] < 8191 ? v1[r] : 8191;
            g_idx2[row0 + r] = v2[r] > 8192 ? v2[r] : 8192;
        }
    }
}

// =============== Kernel 2: weights -> fp16, layout [n][4*1024] ===============
__global__ void __launch_bounds__(256) convert_w(const float* __restrict__ Ww,
                                                 const float* __restrict__ Uw,
                                                 const float* __restrict__ Qrw,
                                                 const float* __restrict__ Qlw) {
    int i = blockIdx.x * 256 + threadIdx.x;      // float4 index, 1M total
    int n  = i >> 10;
    int k4 = i & 1023;
    int kg = k4 * 4;
    int seg = kg >> 10;
    int k   = kg & 1023;
    const float* w = (seg == 0) ? Ww : (seg == 1) ? Uw : (seg == 2) ? Qrw : Qlw;
    float4 v = *(const float4*)(w + (size_t)n * HDIM + k);
    __half2 h0 = __floats2half2_rn(v.x, v.y);
    __half2 h1 = __floats2half2_rn(v.z, v.w);
    uint2 o = make_uint2(*(uint32_t*)&h0, *(uint32_t*)&h1);
    *(uint2*)(g_wh + (size_t)n * KDIM + kg) = o;
}

// =============== Kernel 3: gather + fp16 A matrix ===============
__global__ void __launch_bounds__(256) convert_a(const float* __restrict__ x,
                                                 const float* __restrict__ h_prev,
                                                 const float* __restrict__ memory) {
    const int b = blockIdx.x, tid = threadIdx.x;
    const float* srcs[4];
    srcs[0] = x      + (size_t)b * HDIM;
    srcs[1] = h_prev + (size_t)b * HDIM;
    srcs[2] = memory + (size_t)g_idx1[b] * HDIM;
    srcs[3] = memory + (size_t)g_idx2[b] * HDIM;
    __half* dst = g_ah + (size_t)b * KDIM;
#pragma unroll
    for (int s = 0; s < 4; ++s) {
        float4 v = ((const float4*)srcs[s])[tid];
        __half2 h0 = __floats2half2_rn(v.x, v.y);
        __half2 h1 = __floats2half2_rn(v.z, v.w);
        uint2 o = make_uint2(*(uint32_t*)&h0, *(uint32_t*)&h1);
        ((uint2*)(dst + s * HDIM))[tid] = o;
    }
}

// =============== Kernel 4: fp16 mma.sync GEMM, split-K=4 by segment ===============
__global__ void __launch_bounds__(256, 2) gemm_kernel() {
    extern __shared__ __half smh[];          // [3][A 128x64h SW128 | B 128x64h SW128]

    const int tid = threadIdx.x;
    const int bn0 = blockIdx.x * BN, bm0 = blockIdx.y * BM;
    const int seg = blockIdx.z;              // K segment: 0..3
    const uint32_t smb = smem_u32(smh);

    // ---- loader mapping: 2 threads/row, 4x16B chunks each ----
    const int lrow = tid >> 1;               // 0..127
    const int lh   = tid & 1;
    const __half* aSrc = g_ah + (size_t)(bm0 + lrow) * KDIM + seg * 1024 + lh * 32;
    const __half* bSrc = g_wh + (size_t)(bn0 + lrow) * KDIM + seg * 1024 + lh * 32;
    const uint32_t lmask  = (uint32_t)((lrow & 7) << 4);
    const uint32_t rowOff = (uint32_t)lrow * 128;

    auto issue = [&](int kt, int s) {
        const uint32_t base = smb + (uint32_t)s * STAGEB;
        const __half* as = aSrc + kt * BK;
        const __half* bs = bSrc + kt * BK;
#pragma unroll
        for (int j = 0; j < 4; ++j) {
            const uint32_t cb = (uint32_t)(lh * 64 + j * 16);
            const uint32_t sw = rowOff + (cb ^ lmask);
            cpa16(base + sw,         as + j * 8);
            cpa16(base + 16384 + sw, bs + j * 8);
        }
        cpa_commit();
    };

    issue(0, 0); issue(1, 1);

    // ---- fragment addressing (lane constants) ----
    const int lane = tid & 31, warp = tid >> 5;
    const int wm = warp & 3;                 // m0 = wm*32
    const int wn = warp >> 2;                // n0 = wn*64
    const int l7 = lane & 7;
    const uint32_t xm = (uint32_t)(l7 << 4);
    const int rAb = wm * 32 + (((lane & 15) >> 3) << 3) + l7;      // + mt*16
    const uint32_t hiA = (lane >= 16) ? 16u : 0u;
    const int rBb = wn * 64 + ((lane >= 16) ? 8 : 0) + l7;         // + p*16
    const uint32_t hiB = ((lane & 15) >= 8) ? 16u : 0u;

    float acc[2][8][4];
#pragma unroll
    for (int mt = 0; mt < 2; ++mt)
#pragma unroll
        for (int nt = 0; nt < 8; ++nt)
#pragma unroll
            for (int i = 0; i < 4; ++i) acc[mt][nt][i] = 0.f;

    for (int kt = 0; kt < NTSEG; ++kt) {
        if (kt >= NTSEG - 2) asm volatile("cp.async.wait_group 0;" ::: "memory");
        else                 asm volatile("cp.async.wait_group 1;" ::: "memory");
        __syncthreads();
        if (kt + 2 < NTSEG) issue(kt + 2, (kt + 2) % NSTAGE);  // stage freed at iter kt-1

        const uint32_t sA = smb + (uint32_t)(kt % NSTAGE) * STAGEB;
        const uint32_t sB = sA + 16384;

#pragma unroll
        for (int q = 0; q < 4; ++q) {                        // 4 x k16 per tile
            uint32_t a[2][4];
#pragma unroll
            for (int mt = 0; mt < 2; ++mt)
                ldsm4(a[mt], sA + (uint32_t)(rAb + mt * 16) * 128
                             + (((uint32_t)(q * 32) + hiA) ^ xm));
#pragma unroll
            for (int p = 0; p < 4; ++p) {
                uint32_t b[4];                               // b0/b1 of nt=2p, 2p+1
                ldsm4(b, sB + (uint32_t)(rBb + p * 16) * 128
                          + (((uint32_t)(q * 32) + hiB) ^ xm));
                mma_f16(acc[0][2 * p],     a[0], b[0], b[1]);
                mma_f16(acc[1][2 * p],     a[1], b[0], b[1]);
                mma_f16(acc[0][2 * p + 1], a[0], b[2], b[3]);
                mma_f16(acc[1][2 * p + 1], a[1], b[2], b[3]);
            }
        }
    }

    // ---- epilogue: fp16 partials ----
    const int g = lane >> 2, c = lane & 3;
    __half* pbase = g_part + (size_t)seg * PSZ;
#pragma unroll
    for (int mt = 0; mt < 2; ++mt) {
        const int row0 = bm0 + wm * 32 + mt * 16 + g;
#pragma unroll
        for (int nt = 0; nt < 8; ++nt) {
            const int col = bn0 + wn * 64 + nt * 8 + c * 2;
            __half2 h0 = __floats2half2_rn(acc[mt][nt][0], acc[mt][nt][1]);
            __half2 h1 = __floats2half2_rn(acc[mt][nt][2], acc[mt][nt][3]);
            *(uint32_t*)(pbase + (size_t)row0 * HDIM + col)       = *(uint32_t*)&h0;
            *(uint32_t*)(pbase + (size_t)(row0 + 8) * HDIM + col) = *(uint32_t*)&h1;
        }
    }
}

// =============== Kernel 5: partial-sum + bias + layernorm + sigmoid ===============
__global__ void __launch_bounds__(256) ln_kernel(const float* __restrict__ gamma,
                                                 const float* __restrict__ beta,
                                                 const float* __restrict__ Wb,
                                                 const float* __restrict__ Ub,
                                                 const float* __restrict__ Qrb,
                                                 const float* __restrict__ Qlb,
                                                 float* __restrict__ out) {
    __shared__ float red[16];
    const int row = blockIdx.x, tid = threadIdx.x;
    float4 b0 = ((const float4*)Wb)[tid];
    float4 b1 = ((const float4*)Ub)[tid];
    float4 b2 = ((const float4*)Qrb)[tid];
    float4 b3 = ((const float4*)Qlb)[tid];
    float4 v = make_float4(b0.x + b1.x + b2.x + b3.x,
                           b0.y + b1.y + b2.y + b3.y,
                           b0.z + b1.z + b2.z + b3.z,
                           b0.w + b1.w + b2.w + b3.w);
#pragma unroll
    for (int s = 0; s < 4; ++s) {
        uint2 u = ((const uint2*)(g_part + (size_t)s * PSZ + (size_t)row * HDIM))[tid];
        float2 fa = __half22float2(*(__half2*)&u.x);
        float2 fb = __half22float2(*(__half2*)&u.y);
        v.x += fa.x; v.y += fa.y; v.z += fb.x; v.w += fb.y;
    }
    float s = v.x + v.y + v.z + v.w;
    float q = v.x * v.x + v.y * v.y + v.z * v.z + v.w * v.w;
#pragma unroll
    for (int o = 16; o; o >>= 1) {
        s += __shfl_xor_sync(0xffffffffu, s, o);
        q += __shfl_xor_sync(0xffffffffu, q, o);
    }
    const int lane = tid & 31, w = tid >> 5;
    if (lane == 0) { red[w] = s; red[8 + w] = q; }
    __syncthreads();
    if (tid < 8) {
        s = red[tid]; q = red[8 + tid];
#pragma unroll
        for (int o = 4; o; o >>= 1) {
            s += __shfl_xor_sync(0xffu, s, o);
            q += __shfl_xor_sync(0xffu, q, o);
        }
        if (tid == 0) { red[0] = s; red[8] = q; }
    }
    __syncthreads();
    const float mu  = red[0] * (1.f / HDIM);
    const float var = red[8] * (1.f / HDIM) - mu * mu;
    const float rs  = rsqrtf(var + 1e-5f);
    float4 gm = ((const float4*)gamma)[tid];
    float4 bt = ((const float4*)beta)[tid];
    float4 o4;
    o4.x = 1.f / (1.f + __expf(-((v.x - mu) * rs * gm.x + bt.x)));
    o4.y = 1.f / (1.f + __expf(-((v.y - mu) * rs * gm.y + bt.y)));
    o4.z = 1.f / (1.f + __expf(-((v.z - mu) * rs * gm.z + bt.z)));
    o4.w = 1.f / (1.f + __expf(-((v.w - mu) * rs * gm.w + bt.w)));
    ((float4*)(out + (size_t)row * HDIM))[tid] = o4;
}

// =============== host launch ===============
extern "C" void kernel_launch(void* const* d_in, const int* in_sizes, int n_in,
                              void* d_out, int out_size) {
    const float* x     = (const float*)d_in[0];
    const float* h     = (const float*)d_in[1];
    const float* mem   = (const float*)d_in[2];
    const float* Ww    = (const float*)d_in[3];
    const float* Wb    = (const float*)d_in[4];
    const float* Uw    = (const float*)d_in[5];
    const float* Ub    = (const float*)d_in[6];
    const float* Mw    = (const float*)d_in[7];
    const float* Mb    = (const float*)d_in[8];
    const float* Qrw   = (const float*)d_in[9];
    const float* Qrb   = (const float*)d_in[10];
    const float* Qlw   = (const float*)d_in[11];
    const float* Qlb   = (const float*)d_in[12];
    const float* gamma = (const float*)d_in[13];
    const float* beta  = (const float*)d_in[14];
    float* out = (float*)d_out;

    cudaFuncSetAttribute(idx_kernel,  cudaFuncAttributeMaxDynamicSharedMemorySize, IDX_DYN);
    cudaFuncSetAttribute(gemm_kernel, cudaFuncAttributeMaxDynamicSharedMemorySize, GEMM_DYN);

    idx_kernel<<<NROWS / 32, 256, IDX_DYN>>>(h, Mw, Mb);
    convert_w<<<HDIM * KDIM / 4 / 256, 256>>>(Ww, Uw, Qrw, Qlw);
    convert_a<<<NROWS, 256>>>(x, h, mem);
    gemm_kernel<<<dim3(HDIM / BN, NROWS / BM, 4), 256, GEMM_DYN>>>();
    ln_kernel<<<NROWS, 256>>>(gamma, beta, Wb, Ub, Qrb, Qlb, out);
}